// round 1
// baseline (speedup 1.0000x reference)
#include <cuda_runtime.h>
#include <math.h>

#define B_  2
#define T_  2048
#define D_  1024
#define H_  16
#define HD_ 64
#define M_  (B_*T_)      // 4096 rows

#define THRESH 0.29514f
#define SHARP  15.0f

// ---------------- scratch (device globals: no allocation allowed) ----------------
__device__ float g_xnorm[(size_t)M_*D_];
__device__ float g_q[(size_t)M_*D_];
__device__ float g_k[(size_t)M_*D_];
__device__ float g_v[(size_t)M_*D_];
__device__ float g_gq[(size_t)B_*H_*T_];
__device__ float g_gk[(size_t)B_*H_*T_];
__device__ float g_coll[(size_t)M_*D_];

// ---------------- LayerNorm: one block per row ----------------
__global__ __launch_bounds__(256) void ln_kernel(const float* __restrict__ x,
                                                 const float* __restrict__ w,
                                                 const float* __restrict__ b,
                                                 float* __restrict__ y) {
    int r = blockIdx.x;
    const float* xr = x + (size_t)r * D_;
    float* yr = y + (size_t)r * D_;
    int tid = threadIdx.x;

    float v[4];
    float s = 0.f, ss = 0.f;
#pragma unroll
    for (int i = 0; i < 4; i++) {
        v[i] = xr[tid + i * 256];
        s += v[i];
        ss += v[i] * v[i];
    }
    __shared__ float red[2][8];
#pragma unroll
    for (int o = 16; o > 0; o >>= 1) {
        s  += __shfl_xor_sync(0xffffffffu, s, o);
        ss += __shfl_xor_sync(0xffffffffu, ss, o);
    }
    if ((tid & 31) == 0) { red[0][tid >> 5] = s; red[1][tid >> 5] = ss; }
    __syncthreads();
    if (tid < 32) {
        float a = (tid < 8) ? red[0][tid] : 0.f;
        float c = (tid < 8) ? red[1][tid] : 0.f;
#pragma unroll
        for (int o = 4; o > 0; o >>= 1) {
            a += __shfl_xor_sync(0xffffffffu, a, o);
            c += __shfl_xor_sync(0xffffffffu, c, o);
        }
        if (tid == 0) { red[0][0] = a; red[1][0] = c; }
    }
    __syncthreads();
    float mu   = red[0][0] * (1.f / D_);
    float var  = red[1][0] * (1.f / D_) - mu * mu;
    float rstd = rsqrtf(var + 1e-5f);
#pragma unroll
    for (int i = 0; i < 4; i++) {
        int c = tid + i * 256;
        yr[c] = (v[i] - mu) * rstd * w[c] + b[c];
    }
}

// ---------------- SGEMM: C[MxN] = A[MxK] @ B[KxN] (+ bias) ----------------
// 128x128 block tile, 8x8 per thread, BK=8, 256 threads.
__global__ __launch_bounds__(256) void sgemm_bias(const float* __restrict__ A,
                                                  const float* __restrict__ B,
                                                  const float* __restrict__ bias,
                                                  float* __restrict__ C,
                                                  int M, int N, int K) {
    __shared__ float As[8][128];
    __shared__ float Bs[8][128];

    int tid  = threadIdx.x;
    int row0 = blockIdx.y * 128;
    int col0 = blockIdx.x * 128;

    int aRow = tid >> 1;              // 0..127
    int aCol = (tid & 1) * 4;         // 0 or 4
    int bRow = tid >> 5;              // 0..7
    int bCol = (tid & 31) * 4;        // 0..124

    int tRow = (tid >> 4) * 8;        // 0..120
    int tCol = (tid & 15) * 8;

    float acc[8][8];
#pragma unroll
    for (int i = 0; i < 8; i++)
#pragma unroll
        for (int j = 0; j < 8; j++) acc[i][j] = 0.f;

    for (int k0 = 0; k0 < K; k0 += 8) {
        float4 av = *(const float4*)(A + (size_t)(row0 + aRow) * K + k0 + aCol);
        As[aCol + 0][aRow] = av.x;
        As[aCol + 1][aRow] = av.y;
        As[aCol + 2][aRow] = av.z;
        As[aCol + 3][aRow] = av.w;
        float4 bv = *(const float4*)(B + (size_t)(k0 + bRow) * N + col0 + bCol);
        *(float4*)&Bs[bRow][bCol] = bv;
        __syncthreads();

#pragma unroll
        for (int kk = 0; kk < 8; kk++) {
            float a[8], bb[8];
            *(float4*)&a[0]  = *(const float4*)&As[kk][tRow];
            *(float4*)&a[4]  = *(const float4*)&As[kk][tRow + 4];
            *(float4*)&bb[0] = *(const float4*)&Bs[kk][tCol];
            *(float4*)&bb[4] = *(const float4*)&Bs[kk][tCol + 4];
#pragma unroll
            for (int i = 0; i < 8; i++)
#pragma unroll
                for (int j = 0; j < 8; j++) acc[i][j] = fmaf(a[i], bb[j], acc[i][j]);
        }
        __syncthreads();
    }

#pragma unroll
    for (int i = 0; i < 8; i++) {
        float* cp = C + (size_t)(row0 + tRow + i) * N + col0 + tCol;
        float4 o0, o1;
        if (bias) {
            o0 = make_float4(acc[i][0] + bias[col0 + tCol + 0],
                             acc[i][1] + bias[col0 + tCol + 1],
                             acc[i][2] + bias[col0 + tCol + 2],
                             acc[i][3] + bias[col0 + tCol + 3]);
            o1 = make_float4(acc[i][4] + bias[col0 + tCol + 4],
                             acc[i][5] + bias[col0 + tCol + 5],
                             acc[i][6] + bias[col0 + tCol + 6],
                             acc[i][7] + bias[col0 + tCol + 7]);
        } else {
            o0 = make_float4(acc[i][0], acc[i][1], acc[i][2], acc[i][3]);
            o1 = make_float4(acc[i][4], acc[i][5], acc[i][6], acc[i][7]);
        }
        *(float4*)cp       = o0;
        *(float4*)(cp + 4) = o1;
    }
}

// ---------------- per-head l2 normalize (in place) + gate dot ----------------
// one warp per (row, head)
__global__ __launch_bounds__(256) void norm_gate_kernel(float* __restrict__ Q,
                                                        const float* __restrict__ g,
                                                        float* __restrict__ gate) {
    int gw = (blockIdx.x * blockDim.x + threadIdx.x) >> 5;
    if (gw >= M_ * H_) return;
    int lane = threadIdx.x & 31;
    int r = gw >> 4;          // row in [0, M_)
    int h = gw & (H_ - 1);

    float* qp = Q + (size_t)r * D_ + h * HD_;
    float2 qv = ((float2*)qp)[lane];
    float2 gv = ((const float2*)g)[lane];

    float ss = qv.x * qv.x + qv.y * qv.y;
#pragma unroll
    for (int o = 16; o > 0; o >>= 1) ss += __shfl_xor_sync(0xffffffffu, ss, o);
    float inv = 1.f / fmaxf(sqrtf(ss), 1e-12f);
    qv.x *= inv; qv.y *= inv;
    ((float2*)qp)[lane] = qv;

    float d = qv.x * gv.x + qv.y * gv.y;
#pragma unroll
    for (int o = 16; o > 0; o >>= 1) d += __shfl_xor_sync(0xffffffffu, d, o);
    if (lane == 0) {
        int b = r / T_, t = r % T_;
        gate[((size_t)b * H_ + h) * T_ + t] = d;
    }
}

// ---------------- fused "flash"-style attention ----------------
// block = 64 query rows of one (b,h); loops over 64-row KV tiles.
// No softmax normalization needed: modulation is elementwise.
#define AT_PAD 65
#define SMEM_ATT (3 * 64 * AT_PAD * 4 + 2 * 64 * 4)

extern __shared__ float smem_att[];
__global__ __launch_bounds__(256) void attention_kernel(const float* __restrict__ Q,
                                                        const float* __restrict__ K,
                                                        const float* __restrict__ V,
                                                        const float* __restrict__ GQ,
                                                        const float* __restrict__ GK,
                                                        float* __restrict__ O) {
    float* Qs  = smem_att;                 // 64 x AT_PAD
    float* Ks  = Qs + 64 * AT_PAD;         // 64 x AT_PAD, reused as Ss
    float* Vs  = Ks + 64 * AT_PAD;         // 64 x AT_PAD
    float* gks = Vs + 64 * AT_PAD;         // 64 (gq kept in regs)

    int t0  = blockIdx.x * 64;
    int h   = blockIdx.y;
    int b   = blockIdx.z;
    int tid = threadIdx.x;

    const size_t base  = (size_t)b * T_ * D_ + h * HD_;
    const size_t gbase = ((size_t)b * H_ + h) * T_;

    int ty = tid >> 4, tx = tid & 15;
    int i0 = ty * 4, j0 = tx * 4;          // 4x4 micro-tile

    // load Q tile (64x64) into smem
    for (int idx = tid; idx < 64 * 16; idx += 256) {
        int i = idx >> 4, d4 = (idx & 15) << 2;
        float4 qv = *(const float4*)(Q + base + (size_t)(t0 + i) * D_ + d4);
        float* qd = &Qs[i * AT_PAD + d4];
        qd[0] = qv.x; qd[1] = qv.y; qd[2] = qv.z; qd[3] = qv.w;
    }
    float gqr[4];
#pragma unroll
    for (int r = 0; r < 4; r++) gqr[r] = GQ[gbase + t0 + i0 + r];

    float Cacc[4][4];
#pragma unroll
    for (int r = 0; r < 4; r++)
#pragma unroll
        for (int c = 0; c < 4; c++) Cacc[r][c] = 0.f;

    for (int s0 = 0; s0 < T_; s0 += 64) {
        __syncthreads();   // previous Ss/Vs fully consumed
        // load K, V tiles
        for (int idx = tid; idx < 64 * 16; idx += 256) {
            int j = idx >> 4, d4 = (idx & 15) << 2;
            float4 kv = *(const float4*)(K + base + (size_t)(s0 + j) * D_ + d4);
            float* kd = &Ks[j * AT_PAD + d4];
            kd[0] = kv.x; kd[1] = kv.y; kd[2] = kv.z; kd[3] = kv.w;
            float4 vv = *(const float4*)(V + base + (size_t)(s0 + j) * D_ + d4);
            float* vd = &Vs[j * AT_PAD + d4];
            vd[0] = vv.x; vd[1] = vv.y; vd[2] = vv.z; vd[3] = vv.w;
        }
        if (tid < 64) gks[tid] = GK[gbase + s0 + tid];
        __syncthreads();

        // S = Q @ K^T   (64x64x64)
        float Sacc[4][4];
#pragma unroll
        for (int r = 0; r < 4; r++)
#pragma unroll
            for (int c = 0; c < 4; c++) Sacc[r][c] = 0.f;
#pragma unroll 4
        for (int d = 0; d < 64; d++) {
            float qf[4], kf[4];
#pragma unroll
            for (int r = 0; r < 4; r++) qf[r] = Qs[(i0 + r) * AT_PAD + d];
#pragma unroll
            for (int c = 0; c < 4; c++) kf[c] = Ks[(j0 + c) * AT_PAD + d];
#pragma unroll
            for (int r = 0; r < 4; r++)
#pragma unroll
                for (int c = 0; c < 4; c++) Sacc[r][c] = fmaf(qf[r], kf[c], Sacc[r][c]);
        }

        float gkc[4];
#pragma unroll
        for (int c = 0; c < 4; c++) gkc[c] = gks[j0 + c];

        // modulation: sigmoid((s - TH)*SH) * gq[t] * gk[s]
#pragma unroll
        for (int r = 0; r < 4; r++)
#pragma unroll
            for (int c = 0; c < 4; c++) {
                float sig = 1.f / (1.f + __expf((THRESH - Sacc[r][c]) * SHARP));
                Sacc[r][c] = sig * gqr[r] * gkc[c];
            }

        __syncthreads();   // done reading Ks -> reuse it as Ss
#pragma unroll
        for (int r = 0; r < 4; r++)
#pragma unroll
            for (int c = 0; c < 4; c++) Ks[(i0 + r) * AT_PAD + j0 + c] = Sacc[r][c];
        __syncthreads();

        // C += Ss @ V   (64x64x64)
#pragma unroll 4
        for (int s = 0; s < 64; s++) {
            float sf[4], vf[4];
#pragma unroll
            for (int r = 0; r < 4; r++) sf[r] = Ks[(i0 + r) * AT_PAD + s];
#pragma unroll
            for (int c = 0; c < 4; c++) vf[c] = Vs[s * AT_PAD + j0 + c];
#pragma unroll
            for (int r = 0; r < 4; r++)
#pragma unroll
                for (int c = 0; c < 4; c++) Cacc[r][c] = fmaf(sf[r], vf[c], Cacc[r][c]);
        }
    }

    // write collapse in [b, t, h, d] layout (== reference transpose-back)
#pragma unroll
    for (int r = 0; r < 4; r++) {
        float* op = O + base + (size_t)(t0 + i0 + r) * D_ + j0;
#pragma unroll
        for (int c = 0; c < 4; c++) op[c] = Cacc[r][c];
    }
}

// ---------------- launch ----------------
extern "C" void kernel_launch(void* const* d_in, const int* in_sizes, int n_in,
                              void* d_out, int out_size) {
    const float* x    = (const float*)d_in[0];
    const float* Wq   = (const float*)d_in[1];
    const float* Wk   = (const float*)d_in[2];
    const float* Wv   = (const float*)d_in[3];
    const float* gq   = (const float*)d_in[4];
    const float* gk   = (const float*)d_in[5];
    const float* Wo   = (const float*)d_in[6];
    const float* bo   = (const float*)d_in[7];
    const float* ln_w = (const float*)d_in[8];
    const float* ln_b = (const float*)d_in[9];
    float* out = (float*)d_out;

    float *xn, *q, *k, *v, *gqb, *gkb, *coll;
    cudaGetSymbolAddress((void**)&xn,   g_xnorm);
    cudaGetSymbolAddress((void**)&q,    g_q);
    cudaGetSymbolAddress((void**)&k,    g_k);
    cudaGetSymbolAddress((void**)&v,    g_v);
    cudaGetSymbolAddress((void**)&gqb,  g_gq);
    cudaGetSymbolAddress((void**)&gkb,  g_gk);
    cudaGetSymbolAddress((void**)&coll, g_coll);

    ln_kernel<<<M_, 256>>>(x, ln_w, ln_b, xn);

    dim3 gGemm(D_ / 128, M_ / 128);
    sgemm_bias<<<gGemm, 256>>>(xn, Wq, nullptr, q, M_, D_, D_);
    sgemm_bias<<<gGemm, 256>>>(xn, Wk, nullptr, k, M_, D_, D_);
    sgemm_bias<<<gGemm, 256>>>(x,  Wv, nullptr, v, M_, D_, D_);

    int nWarps = M_ * H_;
    norm_gate_kernel<<<(nWarps * 32 + 255) / 256, 256>>>(q, gq, gqb);
    norm_gate_kernel<<<(nWarps * 32 + 255) / 256, 256>>>(k, gk, gkb);

    cudaFuncSetAttribute(attention_kernel,
                         cudaFuncAttributeMaxDynamicSharedMemorySize, SMEM_ATT);
    attention_kernel<<<dim3(T_ / 64, H_, B_), 256, SMEM_ATT>>>(q, k, v, gqb, gkb, coll);

    sgemm_bias<<<gGemm, 256>>>(coll, Wo, bo, out, M_, D_, D_);
}

// round 3
// speedup vs baseline: 1.0853x; 1.0853x over previous
#include <cuda_runtime.h>
#include <math.h>

#define B_  2
#define T_  2048
#define D_  1024
#define H_  16
#define HD_ 64
#define M_  (B_*T_)      // 4096 rows

#define THRESH 0.29514f
#define SHARP  15.0f

// ---------------- scratch (device globals: no allocation allowed) ----------------
__device__ float g_xnorm[(size_t)M_*D_];
__device__ float g_q[(size_t)M_*D_];
__device__ float g_k[(size_t)M_*D_];
__device__ float g_v[(size_t)M_*D_];
__device__ float g_gq[(size_t)B_*H_*T_];
__device__ float g_gk[(size_t)B_*H_*T_];
__device__ float g_coll[(size_t)M_*D_];

// ---------------- LayerNorm: one block per row ----------------
__global__ __launch_bounds__(256) void ln_kernel(const float* __restrict__ x,
                                                 const float* __restrict__ w,
                                                 const float* __restrict__ b,
                                                 float* __restrict__ y) {
    int r = blockIdx.x;
    const float* xr = x + (size_t)r * D_;
    float* yr = y + (size_t)r * D_;
    int tid = threadIdx.x;

    float v[4];
    float s = 0.f, ss = 0.f;
#pragma unroll
    for (int i = 0; i < 4; i++) {
        v[i] = xr[tid + i * 256];
        s += v[i];
        ss += v[i] * v[i];
    }
    __shared__ float red[2][8];
#pragma unroll
    for (int o = 16; o > 0; o >>= 1) {
        s  += __shfl_xor_sync(0xffffffffu, s, o);
        ss += __shfl_xor_sync(0xffffffffu, ss, o);
    }
    if ((tid & 31) == 0) { red[0][tid >> 5] = s; red[1][tid >> 5] = ss; }
    __syncthreads();
    if (tid < 32) {
        float a = (tid < 8) ? red[0][tid] : 0.f;
        float c = (tid < 8) ? red[1][tid] : 0.f;
#pragma unroll
        for (int o = 4; o > 0; o >>= 1) {
            a += __shfl_xor_sync(0xffffffffu, a, o);
            c += __shfl_xor_sync(0xffffffffu, c, o);
        }
        if (tid == 0) { red[0][0] = a; red[1][0] = c; }
    }
    __syncthreads();
    float mu   = red[0][0] * (1.f / D_);
    float var  = red[1][0] * (1.f / D_) - mu * mu;
    float rstd = rsqrtf(var + 1e-5f);
#pragma unroll
    for (int i = 0; i < 4; i++) {
        int c = tid + i * 256;
        yr[c] = (v[i] - mu) * rstd * w[c] + b[c];
    }
}

// ---------------- SGEMM: C[MxN] = A[MxK] @ B[KxN] (+ bias) ----------------
// 128x128 tile, 8x8 per thread, BK=8, 256 threads, 2-stage smem double buffer.
__global__ __launch_bounds__(256) void sgemm_bias(const float* __restrict__ A,
                                                  const float* __restrict__ B,
                                                  const float* __restrict__ bias,
                                                  float* __restrict__ C,
                                                  int M, int N, int K) {
    __shared__ float As[2][8][128];
    __shared__ float Bs[2][8][132];   // pad 4 to soften read conflicts

    int tid  = threadIdx.x;
    int row0 = blockIdx.y * 128;
    int col0 = blockIdx.x * 128;

    int aRow = tid >> 1;              // 0..127
    int aCol = (tid & 1) * 4;         // 0 or 4
    int bRow = tid >> 5;              // 0..7
    int bCol = (tid & 31) * 4;        // 0..124

    int tRow = (tid >> 4) * 8;        // 0..120
    int tCol = (tid & 15) * 8;

    const float* Aptr = A + (size_t)(row0 + aRow) * K + aCol;
    const float* Bptr = B + (size_t)bRow * N + col0 + bCol;

    float acc[8][8];
#pragma unroll
    for (int i = 0; i < 8; i++)
#pragma unroll
        for (int j = 0; j < 8; j++) acc[i][j] = 0.f;

    // prologue: stage 0
    {
        float4 av = *(const float4*)(Aptr);
        float4 bv = *(const float4*)(Bptr);
        As[0][aCol + 0][aRow] = av.x;
        As[0][aCol + 1][aRow] = av.y;
        As[0][aCol + 2][aRow] = av.z;
        As[0][aCol + 3][aRow] = av.w;
        *(float4*)&Bs[0][bRow][bCol] = bv;
    }
    __syncthreads();

    int buf = 0;
    for (int k0 = 8; k0 <= K; k0 += 8) {
        float4 av, bv;
        bool more = (k0 < K);
        if (more) {
            av = *(const float4*)(Aptr + k0);
            bv = *(const float4*)(Bptr + (size_t)k0 * N);
        }
#pragma unroll
        for (int kk = 0; kk < 8; kk++) {
            float a[8], bb[8];
            *(float4*)&a[0]  = *(const float4*)&As[buf][kk][tRow];
            *(float4*)&a[4]  = *(const float4*)&As[buf][kk][tRow + 4];
            *(float4*)&bb[0] = *(const float4*)&Bs[buf][kk][tCol];
            *(float4*)&bb[4] = *(const float4*)&Bs[buf][kk][tCol + 4];
#pragma unroll
            for (int i = 0; i < 8; i++)
#pragma unroll
                for (int j = 0; j < 8; j++) acc[i][j] = fmaf(a[i], bb[j], acc[i][j]);
        }
        if (more) {
            As[buf ^ 1][aCol + 0][aRow] = av.x;
            As[buf ^ 1][aCol + 1][aRow] = av.y;
            As[buf ^ 1][aCol + 2][aRow] = av.z;
            As[buf ^ 1][aCol + 3][aRow] = av.w;
            *(float4*)&Bs[buf ^ 1][bRow][bCol] = bv;
            __syncthreads();
            buf ^= 1;
        }
    }

#pragma unroll
    for (int i = 0; i < 8; i++) {
        float* cp = C + (size_t)(row0 + tRow + i) * N + col0 + tCol;
        float4 o0, o1;
        if (bias) {
            o0 = make_float4(acc[i][0] + bias[col0 + tCol + 0],
                             acc[i][1] + bias[col0 + tCol + 1],
                             acc[i][2] + bias[col0 + tCol + 2],
                             acc[i][3] + bias[col0 + tCol + 3]);
            o1 = make_float4(acc[i][4] + bias[col0 + tCol + 4],
                             acc[i][5] + bias[col0 + tCol + 5],
                             acc[i][6] + bias[col0 + tCol + 6],
                             acc[i][7] + bias[col0 + tCol + 7]);
        } else {
            o0 = make_float4(acc[i][0], acc[i][1], acc[i][2], acc[i][3]);
            o1 = make_float4(acc[i][4], acc[i][5], acc[i][6], acc[i][7]);
        }
        *(float4*)cp       = o0;
        *(float4*)(cp + 4) = o1;
    }
}

// ---------------- per-head l2 normalize (in place) + gate dot ----------------
__global__ __launch_bounds__(256) void norm_gate_kernel(float* __restrict__ Q,
                                                        const float* __restrict__ g,
                                                        float* __restrict__ gate) {
    int gw = (blockIdx.x * blockDim.x + threadIdx.x) >> 5;
    if (gw >= M_ * H_) return;
    int lane = threadIdx.x & 31;
    int r = gw >> 4;          // row in [0, M_)
    int h = gw & (H_ - 1);

    float* qp = Q + (size_t)r * D_ + h * HD_;
    float2 qv = ((float2*)qp)[lane];
    float2 gv = ((const float2*)g)[lane];

    float ss = qv.x * qv.x + qv.y * qv.y;
#pragma unroll
    for (int o = 16; o > 0; o >>= 1) ss += __shfl_xor_sync(0xffffffffu, ss, o);
    float inv = 1.f / fmaxf(sqrtf(ss), 1e-12f);
    qv.x *= inv; qv.y *= inv;
    ((float2*)qp)[lane] = qv;

    float d = qv.x * gv.x + qv.y * gv.y;
#pragma unroll
    for (int o = 16; o > 0; o >>= 1) d += __shfl_xor_sync(0xffffffffu, d, o);
    if (lane == 0) {
        int b = r / T_, t = r % T_;
        gate[((size_t)b * H_ + h) * T_ + t] = d;
    }
}

// ---------------- fused attention (elementwise gate, no softmax) ----------------
// 64 query rows per block, loop over 64-key tiles of one (b,h).
// All smem tiles row-major 64x64 with XOR swizzle; every smem access is LDS.128/STS.128
// and conflict-free; reduction dims processed in quads (8 LDS.128 per 64 FFMA).
#define SW_(row, g) ((g) ^ (((row) >> 2) & 15))
#define SMEM_ATT (4 * 64 * 64 * 4 + 64 * 4)

extern __shared__ float smem_att[];
__global__ __launch_bounds__(256, 2) void attention_kernel(const float* __restrict__ Q,
                                                           const float* __restrict__ K,
                                                           const float* __restrict__ V,
                                                           const float* __restrict__ GQ,
                                                           const float* __restrict__ GK,
                                                           float* __restrict__ O) {
    float4* Qs = (float4*)smem_att;            // 64 rows x 16 groups
    float4* Ks = Qs + 64 * 16;
    float4* Vs = Ks + 64 * 16;
    float4* Ss = Vs + 64 * 16;
    float*  gks = (float*)(Ss + 64 * 16);      // 64

    int t0  = blockIdx.x * 64;
    int h   = blockIdx.y;
    int b   = blockIdx.z;
    int tid = threadIdx.x;

    const size_t base  = (size_t)b * T_ * D_ + h * HD_;
    const size_t gbase = ((size_t)b * H_ + h) * T_;

    int ty = tid >> 4, tx = tid & 15;
    int i0 = ty * 4;                           // query micro-rows
    // key/value micro-cols group = tx (j0 = 4*tx)

    // load Q tile (swizzled row-major)
    for (int idx = tid; idx < 64 * 16; idx += 256) {
        int r = idx >> 4, g = idx & 15;
        Qs[r * 16 + SW_(r, g)] = *(const float4*)(Q + base + (size_t)(t0 + r) * D_ + g * 4);
    }
    float gqr[4];
#pragma unroll
    for (int r = 0; r < 4; r++) gqr[r] = GQ[gbase + t0 + i0 + r];

    float Cacc[4][4];
#pragma unroll
    for (int r = 0; r < 4; r++)
#pragma unroll
        for (int c = 0; c < 4; c++) Cacc[r][c] = 0.f;

    for (int s0 = 0; s0 < T_; s0 += 64) {
        __syncthreads();   // prev S@V consumers done with Ks/Vs/Ss
        for (int idx = tid; idx < 64 * 16; idx += 256) {
            int r = idx >> 4, g = idx & 15;
            Ks[r * 16 + SW_(r, g)] = *(const float4*)(K + base + (size_t)(s0 + r) * D_ + g * 4);
            Vs[r * 16 + SW_(r, g)] = *(const float4*)(V + base + (size_t)(s0 + r) * D_ + g * 4);
        }
        if (tid < 64) gks[tid] = GK[gbase + s0 + tid];
        __syncthreads();

        // S = Q @ K^T : reduce over d in quads
        float Sacc[4][4];
#pragma unroll
        for (int r = 0; r < 4; r++)
#pragma unroll
            for (int c = 0; c < 4; c++) Sacc[r][c] = 0.f;

#pragma unroll 4
        for (int dq = 0; dq < 16; dq++) {
            float4 qv[4], kv[4];
#pragma unroll
            for (int r = 0; r < 4; r++) qv[r] = Qs[(i0 + r) * 16 + (dq ^ ty)];
#pragma unroll
            for (int c = 0; c < 4; c++) kv[c] = Ks[(4 * tx + c) * 16 + (dq ^ tx)];
#pragma unroll
            for (int r = 0; r < 4; r++)
#pragma unroll
                for (int c = 0; c < 4; c++) {
                    Sacc[r][c] = fmaf(qv[r].x, kv[c].x, Sacc[r][c]);
                    Sacc[r][c] = fmaf(qv[r].y, kv[c].y, Sacc[r][c]);
                    Sacc[r][c] = fmaf(qv[r].z, kv[c].z, Sacc[r][c]);
                    Sacc[r][c] = fmaf(qv[r].w, kv[c].w, Sacc[r][c]);
                }
        }

        float gkc[4];
#pragma unroll
        for (int c = 0; c < 4; c++) gkc[c] = gks[4 * tx + c];

#pragma unroll
        for (int r = 0; r < 4; r++) {
#pragma unroll
            for (int c = 0; c < 4; c++) {
                float sig = 1.f / (1.f + __expf((THRESH - Sacc[r][c]) * SHARP));
                Sacc[r][c] = sig * gqr[r] * gkc[c];
            }
            Ss[(i0 + r) * 16 + (tx ^ ty)] =
                make_float4(Sacc[r][0], Sacc[r][1], Sacc[r][2], Sacc[r][3]);
        }
        __syncthreads();

        // C += S @ V : reduce over s in quads
#pragma unroll 4
        for (int sq = 0; sq < 16; sq++) {
            float4 sv[4], vv[4];
#pragma unroll
            for (int r = 0; r < 4; r++) sv[r] = Ss[(i0 + r) * 16 + (sq ^ ty)];
#pragma unroll
            for (int m = 0; m < 4; m++) vv[m] = Vs[(4 * sq + m) * 16 + (tx ^ sq)];
#pragma unroll
            for (int r = 0; r < 4; r++) {
                Cacc[r][0] = fmaf(sv[r].x, vv[0].x, Cacc[r][0]);
                Cacc[r][1] = fmaf(sv[r].x, vv[0].y, Cacc[r][1]);
                Cacc[r][2] = fmaf(sv[r].x, vv[0].z, Cacc[r][2]);
                Cacc[r][3] = fmaf(sv[r].x, vv[0].w, Cacc[r][3]);
                Cacc[r][0] = fmaf(sv[r].y, vv[1].x, Cacc[r][0]);
                Cacc[r][1] = fmaf(sv[r].y, vv[1].y, Cacc[r][1]);
                Cacc[r][2] = fmaf(sv[r].y, vv[1].z, Cacc[r][2]);
                Cacc[r][3] = fmaf(sv[r].y, vv[1].w, Cacc[r][3]);
                Cacc[r][0] = fmaf(sv[r].z, vv[2].x, Cacc[r][0]);
                Cacc[r][1] = fmaf(sv[r].z, vv[2].y, Cacc[r][1]);
                Cacc[r][2] = fmaf(sv[r].z, vv[2].z, Cacc[r][2]);
                Cacc[r][3] = fmaf(sv[r].z, vv[2].w, Cacc[r][3]);
                Cacc[r][0] = fmaf(sv[r].w, vv[3].x, Cacc[r][0]);
                Cacc[r][1] = fmaf(sv[r].w, vv[3].y, Cacc[r][1]);
                Cacc[r][2] = fmaf(sv[r].w, vv[3].z, Cacc[r][2]);
                Cacc[r][3] = fmaf(sv[r].w, vv[3].w, Cacc[r][3]);
            }
        }
    }

    // write collapse in [b, t, h, d] layout
#pragma unroll
    for (int r = 0; r < 4; r++) {
        float* op = O + base + (size_t)(t0 + i0 + r) * D_ + 4 * tx;
        *(float4*)op = make_float4(Cacc[r][0], Cacc[r][1], Cacc[r][2], Cacc[r][3]);
    }
}

// ---------------- launch ----------------
extern "C" void kernel_launch(void* const* d_in, const int* in_sizes, int n_in,
                              void* d_out, int out_size) {
    const float* x    = (const float*)d_in[0];
    const float* Wq   = (const float*)d_in[1];
    const float* Wk   = (const float*)d_in[2];
    const float* Wv   = (const float*)d_in[3];
    const float* gq   = (const float*)d_in[4];
    const float* gk   = (const float*)d_in[5];
    const float* Wo   = (const float*)d_in[6];
    const float* bo   = (const float*)d_in[7];
    const float* ln_w = (const float*)d_in[8];
    const float* ln_b = (const float*)d_in[9];
    float* out = (float*)d_out;

    float *xn, *q, *k, *v, *gqb, *gkb, *coll;
    cudaGetSymbolAddress((void**)&xn,   g_xnorm);
    cudaGetSymbolAddress((void**)&q,    g_q);
    cudaGetSymbolAddress((void**)&k,    g_k);
    cudaGetSymbolAddress((void**)&v,    g_v);
    cudaGetSymbolAddress((void**)&gqb,  g_gq);
    cudaGetSymbolAddress((void**)&gkb,  g_gk);
    cudaGetSymbolAddress((void**)&coll, g_coll);

    ln_kernel<<<M_, 256>>>(x, ln_w, ln_b, xn);

    dim3 gGemm(D_ / 128, M_ / 128);
    sgemm_bias<<<gGemm, 256>>>(xn, Wq, nullptr, q, M_, D_, D_);
    sgemm_bias<<<gGemm, 256>>>(xn, Wk, nullptr, k, M_, D_, D_);
    sgemm_bias<<<gGemm, 256>>>(x,  Wv, nullptr, v, M_, D_, D_);

    int nWarps = M_ * H_;
    norm_gate_kernel<<<(nWarps * 32 + 255) / 256, 256>>>(q, gq, gqb);
    norm_gate_kernel<<<(nWarps * 32 + 255) / 256, 256>>>(k, gk, gkb);

    cudaFuncSetAttribute(attention_kernel,
                         cudaFuncAttributeMaxDynamicSharedMemorySize, SMEM_ATT);
    attention_kernel<<<dim3(T_ / 64, H_, B_), 256, SMEM_ATT>>>(q, k, v, gqb, gkb, coll);

    sgemm_bias<<<gGemm, 256>>>(coll, Wo, bo, out, M_, D_, D_);
}

// round 4
// speedup vs baseline: 1.1029x; 1.0162x over previous
#include <cuda_runtime.h>
#include <math.h>

#define B_  2
#define T_  2048
#define D_  1024
#define H_  16
#define HD_ 64
#define M_  (B_*T_)      // 4096 rows

#define THRESH 0.29514f
#define SHARP  15.0f

// ---------------- scratch (device globals: no allocation allowed) ----------------
__device__ float g_xnorm[(size_t)M_*D_];
__device__ float g_q[(size_t)M_*D_];
__device__ float g_k[(size_t)M_*D_];
__device__ float g_v[(size_t)M_*D_];
__device__ float g_gq[(size_t)B_*H_*T_];
__device__ float g_gk[(size_t)B_*H_*T_];
__device__ float g_coll[(size_t)M_*D_];

// ---------------- LayerNorm: one block per row ----------------
__global__ __launch_bounds__(256) void ln_kernel(const float* __restrict__ x,
                                                 const float* __restrict__ w,
                                                 const float* __restrict__ b,
                                                 float* __restrict__ y) {
    int r = blockIdx.x;
    const float* xr = x + (size_t)r * D_;
    float* yr = y + (size_t)r * D_;
    int tid = threadIdx.x;

    float v[4];
    float s = 0.f, ss = 0.f;
#pragma unroll
    for (int i = 0; i < 4; i++) {
        v[i] = xr[tid + i * 256];
        s += v[i];
        ss += v[i] * v[i];
    }
    __shared__ float red[2][8];
#pragma unroll
    for (int o = 16; o > 0; o >>= 1) {
        s  += __shfl_xor_sync(0xffffffffu, s, o);
        ss += __shfl_xor_sync(0xffffffffu, ss, o);
    }
    if ((tid & 31) == 0) { red[0][tid >> 5] = s; red[1][tid >> 5] = ss; }
    __syncthreads();
    if (tid < 32) {
        float a = (tid < 8) ? red[0][tid] : 0.f;
        float c = (tid < 8) ? red[1][tid] : 0.f;
#pragma unroll
        for (int o = 4; o > 0; o >>= 1) {
            a += __shfl_xor_sync(0xffffffffu, a, o);
            c += __shfl_xor_sync(0xffffffffu, c, o);
        }
        if (tid == 0) { red[0][0] = a; red[1][0] = c; }
    }
    __syncthreads();
    float mu   = red[0][0] * (1.f / D_);
    float var  = red[1][0] * (1.f / D_) - mu * mu;
    float rstd = rsqrtf(var + 1e-5f);
#pragma unroll
    for (int i = 0; i < 4; i++) {
        int c = tid + i * 256;
        yr[c] = (v[i] - mu) * rstd * w[c] + b[c];
    }
}

// ---------------- SGEMM: C[MxN] = A[MxK] @ B[KxN] (+ bias) ----------------
// 128x128 tile, 8x8 per thread in 4+4 split (rows r..r+3 & r+64..r+67, same for
// cols) -> all smem fragment reads are contiguous/broadcast, conflict-free.
__global__ __launch_bounds__(256) void sgemm_bias(const float* __restrict__ A,
                                                  const float* __restrict__ B,
                                                  const float* __restrict__ bias,
                                                  float* __restrict__ C,
                                                  int M, int N, int K) {
    __shared__ float As[2][8][128];
    __shared__ float Bs[2][8][128];

    int tid  = threadIdx.x;
    int row0 = blockIdx.y * 128;
    int col0 = blockIdx.x * 128;

    int aRow = tid >> 1;              // 0..127
    int aCol = (tid & 1) * 4;         // 0 or 4
    int bRow = tid >> 5;              // 0..7
    int bCol = (tid & 31) * 4;        // 0..124

    int rIdx = (tid >> 4) * 4;        // 0..60
    int cIdx = (tid & 15) * 4;        // 0..60

    const float* Aptr = A + (size_t)(row0 + aRow) * K + aCol;
    const float* Bptr = B + (size_t)bRow * N + col0 + bCol;

    float acc[8][8];
#pragma unroll
    for (int i = 0; i < 8; i++)
#pragma unroll
        for (int j = 0; j < 8; j++) acc[i][j] = 0.f;

    // prologue: stage 0
    {
        float4 av = *(const float4*)(Aptr);
        float4 bv = *(const float4*)(Bptr);
        As[0][aCol + 0][aRow] = av.x;
        As[0][aCol + 1][aRow] = av.y;
        As[0][aCol + 2][aRow] = av.z;
        As[0][aCol + 3][aRow] = av.w;
        *(float4*)&Bs[0][bRow][bCol] = bv;
    }
    __syncthreads();

    int buf = 0;
    for (int k0 = 8; k0 <= K; k0 += 8) {
        float4 av, bv;
        bool more = (k0 < K);
        if (more) {
            av = *(const float4*)(Aptr + k0);
            bv = *(const float4*)(Bptr + (size_t)k0 * N);
        }
#pragma unroll
        for (int kk = 0; kk < 8; kk++) {
            float a[8], bb[8];
            *(float4*)&a[0]  = *(const float4*)&As[buf][kk][rIdx];
            *(float4*)&a[4]  = *(const float4*)&As[buf][kk][rIdx + 64];
            *(float4*)&bb[0] = *(const float4*)&Bs[buf][kk][cIdx];
            *(float4*)&bb[4] = *(const float4*)&Bs[buf][kk][cIdx + 64];
#pragma unroll
            for (int i = 0; i < 8; i++)
#pragma unroll
                for (int j = 0; j < 8; j++) acc[i][j] = fmaf(a[i], bb[j], acc[i][j]);
        }
        if (more) {
            As[buf ^ 1][aCol + 0][aRow] = av.x;
            As[buf ^ 1][aCol + 1][aRow] = av.y;
            As[buf ^ 1][aCol + 2][aRow] = av.z;
            As[buf ^ 1][aCol + 3][aRow] = av.w;
            *(float4*)&Bs[buf ^ 1][bRow][bCol] = bv;
            __syncthreads();
            buf ^= 1;
        }
    }

#pragma unroll
    for (int i = 0; i < 8; i++) {
        int row = row0 + rIdx + ((i < 4) ? i : (60 + i));   // i>=4 -> +64+(i-4)
        float* cp = C + (size_t)row * N + col0;
        float4 o0 = make_float4(acc[i][0], acc[i][1], acc[i][2], acc[i][3]);
        float4 o1 = make_float4(acc[i][4], acc[i][5], acc[i][6], acc[i][7]);
        if (bias) {
            o0.x += bias[col0 + cIdx + 0];  o0.y += bias[col0 + cIdx + 1];
            o0.z += bias[col0 + cIdx + 2];  o0.w += bias[col0 + cIdx + 3];
            o1.x += bias[col0 + cIdx + 64]; o1.y += bias[col0 + cIdx + 65];
            o1.z += bias[col0 + cIdx + 66]; o1.w += bias[col0 + cIdx + 67];
        }
        *(float4*)(cp + cIdx)      = o0;
        *(float4*)(cp + cIdx + 64) = o1;
    }
}

// ---------------- per-head l2 normalize (in place) + gate dot ----------------
__global__ __launch_bounds__(256) void norm_gate_kernel(float* __restrict__ Q,
                                                        const float* __restrict__ g,
                                                        float* __restrict__ gate) {
    int gw = (blockIdx.x * blockDim.x + threadIdx.x) >> 5;
    if (gw >= M_ * H_) return;
    int lane = threadIdx.x & 31;
    int r = gw >> 4;          // row in [0, M_)
    int h = gw & (H_ - 1);

    float* qp = Q + (size_t)r * D_ + h * HD_;
    float2 qv = ((float2*)qp)[lane];
    float2 gv = ((const float2*)g)[lane];

    float ss = qv.x * qv.x + qv.y * qv.y;
#pragma unroll
    for (int o = 16; o > 0; o >>= 1) ss += __shfl_xor_sync(0xffffffffu, ss, o);
    float inv = 1.f / fmaxf(sqrtf(ss), 1e-12f);
    qv.x *= inv; qv.y *= inv;
    ((float2*)qp)[lane] = qv;

    float d = qv.x * gv.x + qv.y * gv.y;
#pragma unroll
    for (int o = 16; o > 0; o >>= 1) d += __shfl_xor_sync(0xffffffffu, d, o);
    if (lane == 0) {
        int b = r / T_, t = r % T_;
        gate[((size_t)b * H_ + h) * T_ + t] = d;
    }
}

// ---------------- fused attention (elementwise gate, no softmax) ----------------
// 64 query rows per block; K/V double-buffered with register prefetch so LDG
// latency overlaps a full compute phase. 2 syncs per KV tile.
#define SW_(row, g) ((g) ^ (((row) >> 2) & 15))
#define SMEM_ATT (6 * 64 * 64 * 4 + 2 * 64 * 4)

extern __shared__ float smem_att[];
__global__ __launch_bounds__(256, 2) void attention_kernel(const float* __restrict__ Q,
                                                           const float* __restrict__ K,
                                                           const float* __restrict__ V,
                                                           const float* __restrict__ GQ,
                                                           const float* __restrict__ GK,
                                                           float* __restrict__ O) {
    float4* Qs    = (float4*)smem_att;          // 64 x 16
    float4* Ks[2] = { Qs + 64 * 16,      Qs + 2 * 64 * 16 };
    float4* Vs[2] = { Qs + 3 * 64 * 16,  Qs + 4 * 64 * 16 };
    float4* Ss    = Qs + 5 * 64 * 16;
    float*  gks   = (float*)(Qs + 6 * 64 * 16); // [2][64]

    int t0  = blockIdx.x * 64;
    int h   = blockIdx.y;
    int b   = blockIdx.z;
    int tid = threadIdx.x;

    const size_t base  = (size_t)b * T_ * D_ + h * HD_;
    const size_t gbase = ((size_t)b * H_ + h) * T_;

    int ty = tid >> 4, tx = tid & 15;
    int i0 = ty * 4;

    // load Q tile (swizzled) + preload KV tile 0
    for (int idx = tid; idx < 64 * 16; idx += 256) {
        int r = idx >> 4, g = idx & 15;
        Qs[r * 16 + SW_(r, g)] = *(const float4*)(Q + base + (size_t)(t0 + r) * D_ + g * 4);
    }
#pragma unroll
    for (int j = 0; j < 4; j++) {
        int idx = tid + j * 256;
        int r = idx >> 4, g = idx & 15;
        Ks[0][r * 16 + SW_(r, g)] = *(const float4*)(K + base + (size_t)r * D_ + g * 4);
        Vs[0][r * 16 + SW_(r, g)] = *(const float4*)(V + base + (size_t)r * D_ + g * 4);
    }
    if (tid < 64) gks[tid] = GK[gbase + tid];

    float gqr[4];
#pragma unroll
    for (int r = 0; r < 4; r++) gqr[r] = GQ[gbase + t0 + i0 + r];

    float Cacc[4][4];
#pragma unroll
    for (int r = 0; r < 4; r++)
#pragma unroll
        for (int c = 0; c < 4; c++) Cacc[r][c] = 0.f;

    __syncthreads();

    int buf = 0;
    for (int s0 = 0; s0 < T_; s0 += 64) {
        bool more = (s0 + 64) < T_;
        // prefetch next tile into registers (latency hidden behind S compute)
        float4 kp[4], vp[4];
        float  gp = 0.f;
        if (more) {
#pragma unroll
            for (int j = 0; j < 4; j++) {
                int idx = tid + j * 256;
                int r = idx >> 4, g = idx & 15;
                kp[j] = *(const float4*)(K + base + (size_t)(s0 + 64 + r) * D_ + g * 4);
                vp[j] = *(const float4*)(V + base + (size_t)(s0 + 64 + r) * D_ + g * 4);
            }
            if (tid < 64) gp = GK[gbase + s0 + 64 + tid];
        }

        // S = Q @ K^T
        float Sacc[4][4];
#pragma unroll
        for (int r = 0; r < 4; r++)
#pragma unroll
            for (int c = 0; c < 4; c++) Sacc[r][c] = 0.f;

        const float4* Kb = Ks[buf];
#pragma unroll 4
        for (int dq = 0; dq < 16; dq++) {
            float4 qv[4], kv[4];
#pragma unroll
            for (int r = 0; r < 4; r++) qv[r] = Qs[(i0 + r) * 16 + (dq ^ ty)];
#pragma unroll
            for (int c = 0; c < 4; c++) kv[c] = Kb[(4 * tx + c) * 16 + (dq ^ tx)];
#pragma unroll
            for (int r = 0; r < 4; r++)
#pragma unroll
                for (int c = 0; c < 4; c++) {
                    Sacc[r][c] = fmaf(qv[r].x, kv[c].x, Sacc[r][c]);
                    Sacc[r][c] = fmaf(qv[r].y, kv[c].y, Sacc[r][c]);
                    Sacc[r][c] = fmaf(qv[r].z, kv[c].z, Sacc[r][c]);
                    Sacc[r][c] = fmaf(qv[r].w, kv[c].w, Sacc[r][c]);
                }
        }

        float gkc[4];
#pragma unroll
        for (int c = 0; c < 4; c++) gkc[c] = gks[buf * 64 + 4 * tx + c];

#pragma unroll
        for (int r = 0; r < 4; r++) {
#pragma unroll
            for (int c = 0; c < 4; c++) {
                float sig = 1.f / (1.f + __expf((THRESH - Sacc[r][c]) * SHARP));
                Sacc[r][c] = sig * gqr[r] * gkc[c];
            }
            Ss[(i0 + r) * 16 + (tx ^ ty)] =
                make_float4(Sacc[r][0], Sacc[r][1], Sacc[r][2], Sacc[r][3]);
        }
        __syncthreads();   // Ss ready; Ks[buf] fully consumed

        // stage next tile into the other buffer
        if (more) {
#pragma unroll
            for (int j = 0; j < 4; j++) {
                int idx = tid + j * 256;
                int r = idx >> 4, g = idx & 15;
                Ks[buf ^ 1][r * 16 + SW_(r, g)] = kp[j];
                Vs[buf ^ 1][r * 16 + SW_(r, g)] = vp[j];
            }
            if (tid < 64) gks[(buf ^ 1) * 64 + tid] = gp;
        }

        // C += S @ V
        const float4* Vb = Vs[buf];
#pragma unroll 4
        for (int sq = 0; sq < 16; sq++) {
            float4 sv[4], vv[4];
#pragma unroll
            for (int r = 0; r < 4; r++) sv[r] = Ss[(i0 + r) * 16 + (sq ^ ty)];
#pragma unroll
            for (int m = 0; m < 4; m++) vv[m] = Vb[(4 * sq + m) * 16 + (tx ^ sq)];
#pragma unroll
            for (int r = 0; r < 4; r++) {
                Cacc[r][0] = fmaf(sv[r].x, vv[0].x, Cacc[r][0]);
                Cacc[r][1] = fmaf(sv[r].x, vv[0].y, Cacc[r][1]);
                Cacc[r][2] = fmaf(sv[r].x, vv[0].z, Cacc[r][2]);
                Cacc[r][3] = fmaf(sv[r].x, vv[0].w, Cacc[r][3]);
                Cacc[r][0] = fmaf(sv[r].y, vv[1].x, Cacc[r][0]);
                Cacc[r][1] = fmaf(sv[r].y, vv[1].y, Cacc[r][1]);
                Cacc[r][2] = fmaf(sv[r].y, vv[1].z, Cacc[r][2]);
                Cacc[r][3] = fmaf(sv[r].y, vv[1].w, Cacc[r][3]);
                Cacc[r][0] = fmaf(sv[r].z, vv[2].x, Cacc[r][0]);
                Cacc[r][1] = fmaf(sv[r].z, vv[2].y, Cacc[r][1]);
                Cacc[r][2] = fmaf(sv[r].z, vv[2].z, Cacc[r][2]);
                Cacc[r][3] = fmaf(sv[r].z, vv[2].w, Cacc[r][3]);
                Cacc[r][0] = fmaf(sv[r].w, vv[3].x, Cacc[r][0]);
                Cacc[r][1] = fmaf(sv[r].w, vv[3].y, Cacc[r][1]);
                Cacc[r][2] = fmaf(sv[r].w, vv[3].z, Cacc[r][2]);
                Cacc[r][3] = fmaf(sv[r].w, vv[3].w, Cacc[r][3]);
            }
        }
        __syncthreads();   // Ss/Vs[buf] consumed before next overwrite
        buf ^= 1;
    }

    // write collapse in [b, t, h, d] layout
#pragma unroll
    for (int r = 0; r < 4; r++) {
        float* op = O + base + (size_t)(t0 + i0 + r) * D_ + 4 * tx;
        *(float4*)op = make_float4(Cacc[r][0], Cacc[r][1], Cacc[r][2], Cacc[r][3]);
    }
}

// ---------------- launch ----------------
extern "C" void kernel_launch(void* const* d_in, const int* in_sizes, int n_in,
                              void* d_out, int out_size) {
    const float* x    = (const float*)d_in[0];
    const float* Wq   = (const float*)d_in[1];
    const float* Wk   = (const float*)d_in[2];
    const float* Wv   = (const float*)d_in[3];
    const float* gq   = (const float*)d_in[4];
    const float* gk   = (const float*)d_in[5];
    const float* Wo   = (const float*)d_in[6];
    const float* bo   = (const float*)d_in[7];
    const float* ln_w = (const float*)d_in[8];
    const float* ln_b = (const float*)d_in[9];
    float* out = (float*)d_out;

    float *xn, *q, *k, *v, *gqb, *gkb, *coll;
    cudaGetSymbolAddress((void**)&xn,   g_xnorm);
    cudaGetSymbolAddress((void**)&q,    g_q);
    cudaGetSymbolAddress((void**)&k,    g_k);
    cudaGetSymbolAddress((void**)&v,    g_v);
    cudaGetSymbolAddress((void**)&gqb,  g_gq);
    cudaGetSymbolAddress((void**)&gkb,  g_gk);
    cudaGetSymbolAddress((void**)&coll, g_coll);

    ln_kernel<<<M_, 256>>>(x, ln_w, ln_b, xn);

    dim3 gGemm(D_ / 128, M_ / 128);
    sgemm_bias<<<gGemm, 256>>>(xn, Wq, nullptr, q, M_, D_, D_);
    sgemm_bias<<<gGemm, 256>>>(xn, Wk, nullptr, k, M_, D_, D_);
    sgemm_bias<<<gGemm, 256>>>(x,  Wv, nullptr, v, M_, D_, D_);

    int nWarps = M_ * H_;
    norm_gate_kernel<<<(nWarps * 32 + 255) / 256, 256>>>(q, gq, gqb);
    norm_gate_kernel<<<(nWarps * 32 + 255) / 256, 256>>>(k, gk, gkb);

    cudaFuncSetAttribute(attention_kernel,
                         cudaFuncAttributeMaxDynamicSharedMemorySize, SMEM_ATT);
    attention_kernel<<<dim3(T_ / 64, H_, B_), 256, SMEM_ATT>>>(q, k, v, gqb, gkb, coll);

    sgemm_bias<<<gGemm, 256>>>(coll, Wo, bo, out, M_, D_, D_);
}

// round 6
// speedup vs baseline: 2.7945x; 2.5338x over previous
#include <cuda_runtime.h>
#include <math.h>

#define B_  2
#define T_  2048
#define D_  1024
#define H_  16
#define HD_ 64
#define M_  (B_*T_)      // 4096 rows

#define THRESH 0.29514f
#define SHARP  15.0f

// ---------------- scratch (device globals: no allocation allowed) ----------------
__device__ float g_xnorm[(size_t)M_*D_];
__device__ float g_q[(size_t)M_*D_];
__device__ float g_k[(size_t)M_*D_];
__device__ float g_v[(size_t)M_*D_];
__device__ float g_gq[(size_t)B_*H_*T_];
__device__ float g_gk[(size_t)B_*H_*T_];
__device__ float g_coll[(size_t)M_*D_];

// ---------------- tf32 / mma helpers ----------------
__device__ __forceinline__ float f2tf(float f) {
    unsigned r; asm("cvt.rna.tf32.f32 %0, %1;" : "=r"(r) : "f"(f));
    return __uint_as_float(r);
}
__device__ __forceinline__ float4 cvt4(float4 v) {
    return make_float4(f2tf(v.x), f2tf(v.y), f2tf(v.z), f2tf(v.w));
}
__device__ __forceinline__ void ldsm4(unsigned r[4], const float* p) {
    unsigned a = (unsigned)__cvta_generic_to_shared((void*)p);
    asm volatile("ldmatrix.sync.aligned.m8n8.x4.shared.b16 {%0,%1,%2,%3}, [%4];"
                 : "=r"(r[0]), "=r"(r[1]), "=r"(r[2]), "=r"(r[3]) : "r"(a));
}
__device__ __forceinline__ void mma8(float c[4], const unsigned a[4], const unsigned b[2]) {
    asm volatile("mma.sync.aligned.m16n8k8.row.col.f32.tf32.tf32.f32 "
                 "{%0,%1,%2,%3}, {%4,%5,%6,%7}, {%8,%9}, {%0,%1,%2,%3};"
                 : "+f"(c[0]), "+f"(c[1]), "+f"(c[2]), "+f"(c[3])
                 : "r"(a[0]), "r"(a[1]), "r"(a[2]), "r"(a[3]), "r"(b[0]), "r"(b[1]));
}

// ---------------- LayerNorm: one block per row ----------------
__global__ __launch_bounds__(256) void ln_kernel(const float* __restrict__ x,
                                                 const float* __restrict__ w,
                                                 const float* __restrict__ b,
                                                 float* __restrict__ y) {
    int r = blockIdx.x;
    const float* xr = x + (size_t)r * D_;
    float* yr = y + (size_t)r * D_;
    int tid = threadIdx.x;

    float v[4];
    float s = 0.f, ss = 0.f;
#pragma unroll
    for (int i = 0; i < 4; i++) {
        v[i] = xr[tid + i * 256];
        s += v[i];
        ss += v[i] * v[i];
    }
    __shared__ float red[2][8];
#pragma unroll
    for (int o = 16; o > 0; o >>= 1) {
        s  += __shfl_xor_sync(0xffffffffu, s, o);
        ss += __shfl_xor_sync(0xffffffffu, ss, o);
    }
    if ((tid & 31) == 0) { red[0][tid >> 5] = s; red[1][tid >> 5] = ss; }
    __syncthreads();
    if (tid < 32) {
        float a = (tid < 8) ? red[0][tid] : 0.f;
        float c = (tid < 8) ? red[1][tid] : 0.f;
#pragma unroll
        for (int o = 4; o > 0; o >>= 1) {
            a += __shfl_xor_sync(0xffffffffu, a, o);
            c += __shfl_xor_sync(0xffffffffu, c, o);
        }
        if (tid == 0) { red[0][0] = a; red[1][0] = c; }
    }
    __syncthreads();
    float mu   = red[0][0] * (1.f / D_);
    float var  = red[1][0] * (1.f / D_) - mu * mu;
    float rstd = rsqrtf(var + 1e-5f);
#pragma unroll
    for (int i = 0; i < 4; i++) {
        int c = tid + i * 256;
        yr[c] = (v[i] - mu) * rstd * w[c] + b[c];
    }
}

// ---------------- tf32 GEMM: C[MxN] = A[MxK] @ B[KxN] (+ bias) ----------------
// 128x128 tile, BK=32, 8 warps (2m x 4n), warp tile 64x32, m16n8k8 mma.
// A smem [128][36] row-major; B smem transposed [128 n][36 k]. stride 36 ≡ 4 (mod 32)
// -> every ldmatrix / STS.128 is bank-conflict-free.
#define SG_STRIDE 36
#define SG_TILE   (128 * SG_STRIDE)
#define SG_SMEM   (4 * SG_TILE * 4)      // 2 bufs x (A + B) = 73728 B

__global__ __launch_bounds__(256, 2) void sgemm_tf32(const float* __restrict__ A,
                                                     const float* __restrict__ B,
                                                     const float* __restrict__ bias,
                                                     float* __restrict__ C,
                                                     int M, int N, int K) {
    extern __shared__ float sm[];
    float* As = sm;                       // [2][SG_TILE]
    float* Bt = sm + 2 * SG_TILE;         // [2][SG_TILE]

    int tid = threadIdx.x;
    int lane = tid & 31, wid = tid >> 5;
    int wm = wid & 1, wn = wid >> 1;
    int li = lane & 7, lj = lane >> 3;
    int row0 = blockIdx.y * 128, col0 = blockIdx.x * 128;

    // staging coords
    int ar = tid >> 1;                    // A row 0..127
    int ac = (tid & 1) * 16;              // A col base
    int bn = tid & 127;                   // B col (n)
    int bkh = (tid >> 7) * 16;            // B k half

    const float* Ap = A + (size_t)(row0 + ar) * K + ac;
    const float* Bp = B + (size_t)bkh * N + col0 + bn;

    float acc[4][4][4];
#pragma unroll
    for (int mt = 0; mt < 4; mt++)
#pragma unroll
        for (int nt = 0; nt < 4; nt++)
#pragma unroll
            for (int c = 0; c < 4; c++) acc[mt][nt][c] = 0.f;

    // prologue: stage 0
#pragma unroll
    for (int i = 0; i < 4; i++)
        *(float4*)&As[ar * SG_STRIDE + ac + 4 * i] = cvt4(*(const float4*)(Ap + 4 * i));
#pragma unroll
    for (int a = 0; a < 4; a++) {
        float4 w = make_float4(f2tf(Bp[(size_t)(4 * a + 0) * N]),
                               f2tf(Bp[(size_t)(4 * a + 1) * N]),
                               f2tf(Bp[(size_t)(4 * a + 2) * N]),
                               f2tf(Bp[(size_t)(4 * a + 3) * N]));
        *(float4*)&Bt[bn * SG_STRIDE + bkh + 4 * a] = w;
    }
    __syncthreads();

    int buf = 0;
    for (int k0 = 32; k0 <= K; k0 += 32) {
        bool more = (k0 < K);
        float4 apre[4];
        float  bpre[16];
        if (more) {
#pragma unroll
            for (int i = 0; i < 4; i++) apre[i] = *(const float4*)(Ap + k0 + 4 * i);
#pragma unroll
            for (int j = 0; j < 16; j++) bpre[j] = Bp[(size_t)(k0 + j) * N];
        }
        const float* Ab = As + buf * SG_TILE;
        const float* Bb = Bt + buf * SG_TILE;
#pragma unroll
        for (int ks = 0; ks < 4; ks++) {
            unsigned af[4][4], bf[2][4];
#pragma unroll
            for (int mt = 0; mt < 4; mt++) {
                int r = wm * 64 + mt * 16 + (lj & 1) * 8 + li;
                int c = ks * 8 + (lj >> 1) * 4;
                ldsm4(af[mt], Ab + r * SG_STRIDE + c);
            }
#pragma unroll
            for (int p = 0; p < 2; p++) {
                int r = wn * 32 + p * 16 + (lj >> 1) * 8 + li;
                int c = ks * 8 + (lj & 1) * 4;
                ldsm4(bf[p], Bb + r * SG_STRIDE + c);
            }
#pragma unroll
            for (int mt = 0; mt < 4; mt++)
#pragma unroll
                for (int nt = 0; nt < 4; nt++)
                    mma8(acc[mt][nt], af[mt], &bf[nt >> 1][(nt & 1) * 2]);
        }
        if (more) {
            float* An = As + (buf ^ 1) * SG_TILE;
            float* Bn = Bt + (buf ^ 1) * SG_TILE;
#pragma unroll
            for (int i = 0; i < 4; i++)
                *(float4*)&An[ar * SG_STRIDE + ac + 4 * i] = cvt4(apre[i]);
#pragma unroll
            for (int a = 0; a < 4; a++) {
                float4 w = make_float4(f2tf(bpre[4 * a + 0]), f2tf(bpre[4 * a + 1]),
                                       f2tf(bpre[4 * a + 2]), f2tf(bpre[4 * a + 3]));
                *(float4*)&Bn[bn * SG_STRIDE + bkh + 4 * a] = w;
            }
            __syncthreads();
            buf ^= 1;
        }
    }

    // epilogue
#pragma unroll
    for (int mt = 0; mt < 4; mt++) {
        int r = row0 + wm * 64 + mt * 16 + (lane >> 2);
#pragma unroll
        for (int nt = 0; nt < 4; nt++) {
            int c = col0 + wn * 32 + nt * 8 + 2 * (lane & 3);
            float2 v0 = make_float2(acc[mt][nt][0], acc[mt][nt][1]);
            float2 v1 = make_float2(acc[mt][nt][2], acc[mt][nt][3]);
            if (bias) {
                float b0 = bias[c], b1 = bias[c + 1];
                v0.x += b0; v0.y += b1; v1.x += b0; v1.y += b1;
            }
            *(float2*)(C + (size_t)r * N + c)       = v0;
            *(float2*)(C + (size_t)(r + 8) * N + c) = v1;
        }
    }
}

// ---------------- per-head l2 normalize (in place) + gate dot ----------------
__global__ __launch_bounds__(256) void norm_gate_kernel(float* __restrict__ Q,
                                                        const float* __restrict__ g,
                                                        float* __restrict__ gate) {
    int gw = (blockIdx.x * blockDim.x + threadIdx.x) >> 5;
    if (gw >= M_ * H_) return;
    int lane = threadIdx.x & 31;
    int r = gw >> 4;
    int h = gw & (H_ - 1);

    float* qp = Q + (size_t)r * D_ + h * HD_;
    float2 qv = ((float2*)qp)[lane];
    float2 gv = ((const float2*)g)[lane];

    float ss = qv.x * qv.x + qv.y * qv.y;
#pragma unroll
    for (int o = 16; o > 0; o >>= 1) ss += __shfl_xor_sync(0xffffffffu, ss, o);
    float inv = 1.f / fmaxf(sqrtf(ss), 1e-12f);
    qv.x *= inv; qv.y *= inv;
    ((float2*)qp)[lane] = qv;

    float d = qv.x * gv.x + qv.y * gv.y;
#pragma unroll
    for (int o = 16; o > 0; o >>= 1) d += __shfl_xor_sync(0xffffffffu, d, o);
    if (lane == 0) {
        int b = r / T_, t = r % T_;
        gate[((size_t)b * H_ + h) * T_ + t] = d;
    }
}

// ---------------- fused attention with tf32 mma ----------------
// 64 q-rows per block, 8 warps (2m x 4n): warp S-tile 32x16.
// Qs/Ks/Ss row-major [64][68]; Vt transposed [d][s] = [64][68]. 68 ≡ 4 (mod 32).
#define AT_STRIDE 68
#define AT_TILE   (64 * AT_STRIDE)
#define SMEM_ATT  ((6 * AT_TILE + 64 + 128) * 4)

__global__ __launch_bounds__(256, 2) void attention_tf32(const float* __restrict__ Q,
                                                         const float* __restrict__ K,
                                                         const float* __restrict__ V,
                                                         const float* __restrict__ GQ,
                                                         const float* __restrict__ GK,
                                                         float* __restrict__ O) {
    extern __shared__ float sm[];
    float* Qs  = sm;                       // [64][68]
    float* Ks0 = Qs  + AT_TILE;            // [2][64][68]
    float* Vt0 = Ks0 + 2 * AT_TILE;        // [2][64][68] (transposed)
    float* Ss  = Vt0 + 2 * AT_TILE;        // [64][68]
    float* gqs = Ss + AT_TILE;             // [64]
    float* gks = gqs + 64;                 // [2][64]

    int t0  = blockIdx.x * 64;
    int h   = blockIdx.y;
    int b   = blockIdx.z;
    int tid = threadIdx.x;
    int lane = tid & 31, wid = tid >> 5;
    int wm = wid & 1, wn = wid >> 1;
    int li = lane & 7, lj = lane >> 3;

    const size_t base  = (size_t)b * T_ * D_ + h * HD_;
    const size_t gbase = ((size_t)b * H_ + h) * T_;

    // V-transpose staging coords
    int vd = tid & 63;                     // d
    int vs0 = (tid >> 6) * 16;             // s base (16 rows per thread)

    // Q load + KV tile 0
#pragma unroll
    for (int j = 0; j < 4; j++) {
        int idx = tid + j * 256;
        int r = idx >> 4, g = (idx & 15) * 4;
        Qs[r * AT_STRIDE + g + 0] = 0.f;   // placeholder to keep compiler calm (overwritten)
        *(float4*)&Qs[r * AT_STRIDE + g] =
            cvt4(*(const float4*)(Q + base + (size_t)(t0 + r) * D_ + g));
        *(float4*)&Ks0[r * AT_STRIDE + g] =
            cvt4(*(const float4*)(K + base + (size_t)r * D_ + g));
    }
#pragma unroll
    for (int a = 0; a < 4; a++) {
        float4 w = make_float4(f2tf(V[base + (size_t)(vs0 + 4 * a + 0) * D_ + vd]),
                               f2tf(V[base + (size_t)(vs0 + 4 * a + 1) * D_ + vd]),
                               f2tf(V[base + (size_t)(vs0 + 4 * a + 2) * D_ + vd]),
                               f2tf(V[base + (size_t)(vs0 + 4 * a + 3) * D_ + vd]));
        *(float4*)&Vt0[vd * AT_STRIDE + vs0 + 4 * a] = w;
    }
    if (tid < 64) {
        gqs[tid] = GQ[gbase + t0 + tid];
        gks[tid] = GK[gbase + tid];
    }

    float acc[2][2][4];
#pragma unroll
    for (int mt = 0; mt < 2; mt++)
#pragma unroll
        for (int nt = 0; nt < 2; nt++)
#pragma unroll
            for (int c = 0; c < 4; c++) acc[mt][nt][c] = 0.f;

    __syncthreads();

    int buf = 0;
    for (int s0 = 0; s0 < T_; s0 += 64) {
        bool more = (s0 + 64) < T_;
        float4 kp[4];
        float  vp[16];
        float  gp = 0.f;
        if (more) {
#pragma unroll
            for (int j = 0; j < 4; j++) {
                int idx = tid + j * 256;
                int r = idx >> 4, g = (idx & 15) * 4;
                kp[j] = *(const float4*)(K + base + (size_t)(s0 + 64 + r) * D_ + g);
            }
#pragma unroll
            for (int j = 0; j < 16; j++)
                vp[j] = V[base + (size_t)(s0 + 64 + vs0 + j) * D_ + vd];
            if (tid < 64) gp = GK[gbase + s0 + 64 + tid];
        }

        // ---- S = Q @ K^T ----
        const float* Kb = Ks0 + buf * AT_TILE;
        float sacc[2][2][4];
#pragma unroll
        for (int mt = 0; mt < 2; mt++)
#pragma unroll
            for (int nt = 0; nt < 2; nt++)
#pragma unroll
                for (int c = 0; c < 4; c++) sacc[mt][nt][c] = 0.f;

#pragma unroll
        for (int ks = 0; ks < 8; ks++) {
            unsigned af[2][4], bfr[4];
#pragma unroll
            for (int mt = 0; mt < 2; mt++) {
                int r = wm * 32 + mt * 16 + (lj & 1) * 8 + li;
                int c = ks * 8 + (lj >> 1) * 4;
                ldsm4(af[mt], Qs + r * AT_STRIDE + c);
            }
            {
                int r = wn * 16 + (lj >> 1) * 8 + li;
                int c = ks * 8 + (lj & 1) * 4;
                ldsm4(bfr, Kb + r * AT_STRIDE + c);
            }
#pragma unroll
            for (int mt = 0; mt < 2; mt++)
#pragma unroll
                for (int nt = 0; nt < 2; nt++)
                    mma8(sacc[mt][nt], af[mt], &bfr[nt * 2]);
        }

        // ---- gate + store S to smem ----
#pragma unroll
        for (int mt = 0; mt < 2; mt++) {
            int qrow = wm * 32 + mt * 16 + (lane >> 2);
            float gq0 = gqs[qrow], gq1 = gqs[qrow + 8];
#pragma unroll
            for (int nt = 0; nt < 2; nt++) {
                int scol = wn * 16 + nt * 8 + 2 * (lane & 3);
                float gk0 = gks[buf * 64 + scol], gk1 = gks[buf * 64 + scol + 1];
                float s0v = 1.f / (1.f + __expf((THRESH - sacc[mt][nt][0]) * SHARP)) * gq0 * gk0;
                float s1v = 1.f / (1.f + __expf((THRESH - sacc[mt][nt][1]) * SHARP)) * gq0 * gk1;
                float s2v = 1.f / (1.f + __expf((THRESH - sacc[mt][nt][2]) * SHARP)) * gq1 * gk0;
                float s3v = 1.f / (1.f + __expf((THRESH - sacc[mt][nt][3]) * SHARP)) * gq1 * gk1;
                *(float2*)&Ss[qrow * AT_STRIDE + scol]       = make_float2(f2tf(s0v), f2tf(s1v));
                *(float2*)&Ss[(qrow + 8) * AT_STRIDE + scol] = make_float2(f2tf(s2v), f2tf(s3v));
            }
        }
        __syncthreads();   // Ss visible; all reads of Ks[buf^1]/Vt[buf^1] long done

        // stage prefetched tile into other buffer
        if (more) {
            float* Kn = Ks0 + (buf ^ 1) * AT_TILE;
            float* Vn = Vt0 + (buf ^ 1) * AT_TILE;
#pragma unroll
            for (int j = 0; j < 4; j++) {
                int idx = tid + j * 256;
                int r = idx >> 4, g = (idx & 15) * 4;
                *(float4*)&Kn[r * AT_STRIDE + g] = cvt4(kp[j]);
            }
#pragma unroll
            for (int a = 0; a < 4; a++) {
                float4 w = make_float4(f2tf(vp[4 * a + 0]), f2tf(vp[4 * a + 1]),
                                       f2tf(vp[4 * a + 2]), f2tf(vp[4 * a + 3]));
                *(float4*)&Vn[vd * AT_STRIDE + vs0 + 4 * a] = w;
            }
            if (tid < 64) gks[(buf ^ 1) * 64 + tid] = gp;
        }

        // ---- C += S @ V ----
        const float* Vb = Vt0 + buf * AT_TILE;
#pragma unroll
        for (int ks = 0; ks < 8; ks++) {
            unsigned af[2][4], bfr[4];
#pragma unroll
            for (int mt = 0; mt < 2; mt++) {
                int r = wm * 32 + mt * 16 + (lj & 1) * 8 + li;
                int c = ks * 8 + (lj >> 1) * 4;
                ldsm4(af[mt], Ss + r * AT_STRIDE + c);
            }
            {
                int r = wn * 16 + (lj >> 1) * 8 + li;   // d rows of Vt
                int c = ks * 8 + (lj & 1) * 4;          // s cols
                ldsm4(bfr, Vb + r * AT_STRIDE + c);
            }
#pragma unroll
            for (int mt = 0; mt < 2; mt++)
#pragma unroll
                for (int nt = 0; nt < 2; nt++)
                    mma8(acc[mt][nt], af[mt], &bfr[nt * 2]);
        }
        __syncthreads();   // Ss / Vt[buf] consumed before next overwrite
        buf ^= 1;
    }

    // ---- write collapse [b, t, h, d] ----
#pragma unroll
    for (int mt = 0; mt < 2; mt++) {
        int row = wm * 32 + mt * 16 + (lane >> 2);
#pragma unroll
        for (int nt = 0; nt < 2; nt++) {
            int col = wn * 16 + nt * 8 + 2 * (lane & 3);
            *(float2*)(O + base + (size_t)(t0 + row) * D_ + col) =
                make_float2(acc[mt][nt][0], acc[mt][nt][1]);
            *(float2*)(O + base + (size_t)(t0 + row + 8) * D_ + col) =
                make_float2(acc[mt][nt][2], acc[mt][nt][3]);
        }
    }
}

// ---------------- launch ----------------
extern "C" void kernel_launch(void* const* d_in, const int* in_sizes, int n_in,
                              void* d_out, int out_size) {
    const float* x    = (const float*)d_in[0];
    const float* Wq   = (const float*)d_in[1];
    const float* Wk   = (const float*)d_in[2];
    const float* Wv   = (const float*)d_in[3];
    const float* gq   = (const float*)d_in[4];
    const float* gk   = (const float*)d_in[5];
    const float* Wo   = (const float*)d_in[6];
    const float* bo   = (const float*)d_in[7];
    const float* ln_w = (const float*)d_in[8];
    const float* ln_b = (const float*)d_in[9];
    float* out = (float*)d_out;

    float *xn, *q, *k, *v, *gqb, *gkb, *coll;
    cudaGetSymbolAddress((void**)&xn,   g_xnorm);
    cudaGetSymbolAddress((void**)&q,    g_q);
    cudaGetSymbolAddress((void**)&k,    g_k);
    cudaGetSymbolAddress((void**)&v,    g_v);
    cudaGetSymbolAddress((void**)&gqb,  g_gq);
    cudaGetSymbolAddress((void**)&gkb,  g_gk);
    cudaGetSymbolAddress((void**)&coll, g_coll);

    cudaFuncSetAttribute(sgemm_tf32,
                         cudaFuncAttributeMaxDynamicSharedMemorySize, SG_SMEM);
    cudaFuncSetAttribute(attention_tf32,
                         cudaFuncAttributeMaxDynamicSharedMemorySize, SMEM_ATT);

    ln_kernel<<<M_, 256>>>(x, ln_w, ln_b, xn);

    dim3 gGemm(D_ / 128, M_ / 128);
    sgemm_tf32<<<gGemm, 256, SG_SMEM>>>(xn, Wq, nullptr, q, M_, D_, D_);
    sgemm_tf32<<<gGemm, 256, SG_SMEM>>>(xn, Wk, nullptr, k, M_, D_, D_);
    sgemm_tf32<<<gGemm, 256, SG_SMEM>>>(x,  Wv, nullptr, v, M_, D_, D_);

    int nWarps = M_ * H_;
    norm_gate_kernel<<<(nWarps * 32 + 255) / 256, 256>>>(q, gq, gqb);
    norm_gate_kernel<<<(nWarps * 32 + 255) / 256, 256>>>(k, gk, gkb);

    attention_tf32<<<dim3(T_ / 64, H_, B_), 256, SMEM_ATT>>>(q, k, v, gqb, gkb, coll);

    sgemm_tf32<<<gGemm, 256, SG_SMEM>>>(coll, Wo, bo, out, M_, D_, D_);
}

// round 7
// speedup vs baseline: 4.3454x; 1.5550x over previous
#include <cuda_runtime.h>
#include <cuda_fp16.h>
#include <math.h>

#define B_  2
#define T_  2048
#define D_  1024
#define H_  16
#define HD_ 64
#define M_  (B_*T_)      // 4096 rows

#define THRESH 0.29514f
#define SHARP  15.0f

// ---------------- scratch (device globals: no allocation allowed) ----------------
__device__ __half g_xh[(size_t)M_*D_];
__device__ __half g_xnh[(size_t)M_*D_];
__device__ __half g_vh[(size_t)M_*D_];
__device__ __half g_qh[(size_t)M_*D_];
__device__ __half g_kh[(size_t)M_*D_];
__device__ __half g_collh[(size_t)M_*D_];
__device__ float  g_q[(size_t)M_*D_];
__device__ float  g_k[(size_t)M_*D_];
__device__ float  g_gq[(size_t)B_*H_*T_];
__device__ float  g_gk[(size_t)B_*H_*T_];

// ---------------- helpers ----------------
__device__ __forceinline__ void ldsm4(unsigned r[4], const void* p) {
    unsigned a = (unsigned)__cvta_generic_to_shared(p);
    asm volatile("ldmatrix.sync.aligned.m8n8.x4.shared.b16 {%0,%1,%2,%3}, [%4];"
                 : "=r"(r[0]), "=r"(r[1]), "=r"(r[2]), "=r"(r[3]) : "r"(a));
}
__device__ __forceinline__ void ldsm4t(unsigned r[4], const void* p) {
    unsigned a = (unsigned)__cvta_generic_to_shared(p);
    asm volatile("ldmatrix.sync.aligned.m8n8.x4.trans.shared.b16 {%0,%1,%2,%3}, [%4];"
                 : "=r"(r[0]), "=r"(r[1]), "=r"(r[2]), "=r"(r[3]) : "r"(a));
}
__device__ __forceinline__ void mma16(float c[4], const unsigned a[4],
                                      unsigned b0, unsigned b1) {
    asm volatile("mma.sync.aligned.m16n8k16.row.col.f32.f16.f16.f32 "
                 "{%0,%1,%2,%3}, {%4,%5,%6,%7}, {%8,%9}, {%0,%1,%2,%3};"
                 : "+f"(c[0]), "+f"(c[1]), "+f"(c[2]), "+f"(c[3])
                 : "r"(a[0]), "r"(a[1]), "r"(a[2]), "r"(a[3]), "r"(b0), "r"(b1));
}
__device__ __forceinline__ unsigned pkh(float a, float b) {
    __half2 h = __floats2half2_rn(a, b);
    return *(unsigned*)&h;
}
#define CPA16(dst, src) asm volatile("cp.async.cg.shared.global [%0], [%1], 16;" \
    :: "r"((unsigned)__cvta_generic_to_shared(dst)), "l"(src))
#define CPC()  asm volatile("cp.async.commit_group;")
#define CPW0() asm volatile("cp.async.wait_group 0;" ::: "memory")

// ---------------- LayerNorm -> half outputs (x and x_norm) ----------------
__global__ __launch_bounds__(256) void ln_kernel(const float* __restrict__ x,
                                                 const float* __restrict__ w,
                                                 const float* __restrict__ b,
                                                 __half* __restrict__ xh,
                                                 __half* __restrict__ xnh) {
    int r = blockIdx.x;
    const float* xr = x + (size_t)r * D_;
    int tid = threadIdx.x;

    float v[4];
    float s = 0.f, ss = 0.f;
#pragma unroll
    for (int i = 0; i < 4; i++) {
        v[i] = xr[tid + i * 256];
        s += v[i];
        ss += v[i] * v[i];
    }
    __shared__ float red[2][8];
#pragma unroll
    for (int o = 16; o > 0; o >>= 1) {
        s  += __shfl_xor_sync(0xffffffffu, s, o);
        ss += __shfl_xor_sync(0xffffffffu, ss, o);
    }
    if ((tid & 31) == 0) { red[0][tid >> 5] = s; red[1][tid >> 5] = ss; }
    __syncthreads();
    if (tid < 32) {
        float a = (tid < 8) ? red[0][tid] : 0.f;
        float c = (tid < 8) ? red[1][tid] : 0.f;
#pragma unroll
        for (int o = 4; o > 0; o >>= 1) {
            a += __shfl_xor_sync(0xffffffffu, a, o);
            c += __shfl_xor_sync(0xffffffffu, c, o);
        }
        if (tid == 0) { red[0][0] = a; red[1][0] = c; }
    }
    __syncthreads();
    float mu   = red[0][0] * (1.f / D_);
    float var  = red[1][0] * (1.f / D_) - mu * mu;
    float rstd = rsqrtf(var + 1e-5f);
#pragma unroll
    for (int i = 0; i < 4; i++) {
        int c = tid + i * 256;
        xh[(size_t)r * D_ + c]  = __float2half_rn(v[i]);
        xnh[(size_t)r * D_ + c] = __float2half_rn((v[i] - mu) * rstd * w[c] + b[c]);
    }
}

// ---------------- fp16 GEMM: C = A(half)[MxK] @ B(f32->half)[KxN] (+bias) ----
// 128x128 tile, BK=32, 8 warps (2m x 4n), warp 64x32, m16n8k16.
// A smem [128][40] halves (cp.async); B smem transposed [128n][40k] halves.
#define HG_STRIDE 40
#define HG_TILE   (128 * HG_STRIDE)
#define HG_SMEM   (4 * HG_TILE * 2)      // 2 bufs x (A+B) halves = 40960 B

__global__ __launch_bounds__(256, 2) void hgemm(const __half* __restrict__ A,
                                                const float* __restrict__ B,
                                                const float* __restrict__ bias,
                                                float* __restrict__ Cf,
                                                __half* __restrict__ Ch,
                                                int M, int N, int K) {
    extern __shared__ __half hsm[];
    __half* As = hsm;                    // [2][HG_TILE]
    __half* Bt = hsm + 2 * HG_TILE;      // [2][HG_TILE]

    int tid = threadIdx.x;
    int lane = tid & 31, wid = tid >> 5;
    int wm = wid & 1, wn = wid >> 1;
    int row0 = blockIdx.y * 128, col0 = blockIdx.x * 128;

    int l15 = lane & 15, lh8 = (lane >> 4) * 8;

    // A staging coords (cp.async): 512 chunks of 16B, 2 per thread
    // B staging coords: bn = n col, bkh = k half (16 rows)
    int bn = tid & 127, bkh = (tid >> 7) * 16;
    const float* Bp = B + (size_t)bkh * N + col0 + bn;

    float acc[4][4][4];
#pragma unroll
    for (int mt = 0; mt < 4; mt++)
#pragma unroll
        for (int nt = 0; nt < 4; nt++)
#pragma unroll
            for (int c = 0; c < 4; c++) acc[mt][nt][c] = 0.f;

    // prologue: stage 0
#pragma unroll
    for (int j = 0; j < 2; j++) {
        int idx = tid + j * 256;
        int r = idx >> 2, c = (idx & 3) * 8;
        CPA16(&As[r * HG_STRIDE + c], A + (size_t)(row0 + r) * K + c);
    }
    CPC();
    {
        float bp[16];
#pragma unroll
        for (int j = 0; j < 16; j++) bp[j] = Bp[(size_t)j * N];
        unsigned wv[8];
#pragma unroll
        for (int j = 0; j < 8; j++) wv[j] = pkh(bp[2 * j], bp[2 * j + 1]);
        *(uint4*)&Bt[bn * HG_STRIDE + bkh]     = make_uint4(wv[0], wv[1], wv[2], wv[3]);
        *(uint4*)&Bt[bn * HG_STRIDE + bkh + 8] = make_uint4(wv[4], wv[5], wv[6], wv[7]);
    }
    CPW0();
    __syncthreads();

    int buf = 0;
    for (int k0 = 32; k0 <= K; k0 += 32) {
        bool more = (k0 < K);
        float bp[16];
        if (more) {
#pragma unroll
            for (int j = 0; j < 2; j++) {
                int idx = tid + j * 256;
                int r = idx >> 2, c = (idx & 3) * 8;
                CPA16(&As[(buf ^ 1) * HG_TILE + r * HG_STRIDE + c],
                      A + (size_t)(row0 + r) * K + k0 + c);
            }
            CPC();
#pragma unroll
            for (int j = 0; j < 16; j++) bp[j] = Bp[(size_t)(k0 + j) * N];
        }
        const __half* Ab = As + buf * HG_TILE;
        const __half* Bb = Bt + buf * HG_TILE;
#pragma unroll
        for (int ks = 0; ks < 2; ks++) {
            unsigned af[4][4], bf[2][4];
#pragma unroll
            for (int mt = 0; mt < 4; mt++)
                ldsm4(af[mt], Ab + (wm * 64 + mt * 16 + l15) * HG_STRIDE + ks * 16 + lh8);
#pragma unroll
            for (int p = 0; p < 2; p++)
                ldsm4(bf[p], Bb + (wn * 32 + p * 16 + l15) * HG_STRIDE + ks * 16 + lh8);
#pragma unroll
            for (int mt = 0; mt < 4; mt++)
#pragma unroll
                for (int nt = 0; nt < 4; nt++)
                    mma16(acc[mt][nt], af[mt],
                          bf[nt >> 1][nt & 1], bf[nt >> 1][(nt & 1) + 2]);
        }
        if (more) {
            unsigned wv[8];
#pragma unroll
            for (int j = 0; j < 8; j++) wv[j] = pkh(bp[2 * j], bp[2 * j + 1]);
            __half* Bn = Bt + (buf ^ 1) * HG_TILE;
            *(uint4*)&Bn[bn * HG_STRIDE + bkh]     = make_uint4(wv[0], wv[1], wv[2], wv[3]);
            *(uint4*)&Bn[bn * HG_STRIDE + bkh + 8] = make_uint4(wv[4], wv[5], wv[6], wv[7]);
            CPW0();
            __syncthreads();
            buf ^= 1;
        }
    }

    // epilogue
#pragma unroll
    for (int mt = 0; mt < 4; mt++) {
        int r = row0 + wm * 64 + mt * 16 + (lane >> 2);
#pragma unroll
        for (int nt = 0; nt < 4; nt++) {
            int c = col0 + wn * 32 + nt * 8 + 2 * (lane & 3);
            if (Ch) {
                *(__half2*)(Ch + (size_t)r * N + c) =
                    __floats2half2_rn(acc[mt][nt][0], acc[mt][nt][1]);
                *(__half2*)(Ch + (size_t)(r + 8) * N + c) =
                    __floats2half2_rn(acc[mt][nt][2], acc[mt][nt][3]);
            } else {
                float2 v0 = make_float2(acc[mt][nt][0], acc[mt][nt][1]);
                float2 v1 = make_float2(acc[mt][nt][2], acc[mt][nt][3]);
                if (bias) {
                    float b0 = bias[c], b1 = bias[c + 1];
                    v0.x += b0; v0.y += b1; v1.x += b0; v1.y += b1;
                }
                *(float2*)(Cf + (size_t)r * N + c)       = v0;
                *(float2*)(Cf + (size_t)(r + 8) * N + c) = v1;
            }
        }
    }
}

// ---------------- per-head l2 normalize -> half + gate dot ----------------
__global__ __launch_bounds__(256) void norm_gate_kernel(const float* __restrict__ Q,
                                                        __half* __restrict__ Qh,
                                                        const float* __restrict__ g,
                                                        float* __restrict__ gate) {
    int gw = (blockIdx.x * blockDim.x + threadIdx.x) >> 5;
    if (gw >= M_ * H_) return;
    int lane = threadIdx.x & 31;
    int r = gw >> 4;
    int h = gw & (H_ - 1);

    const float* qp = Q + (size_t)r * D_ + h * HD_;
    float2 qv = ((const float2*)qp)[lane];
    float2 gv = ((const float2*)g)[lane];

    float ss = qv.x * qv.x + qv.y * qv.y;
#pragma unroll
    for (int o = 16; o > 0; o >>= 1) ss += __shfl_xor_sync(0xffffffffu, ss, o);
    float inv = 1.f / fmaxf(sqrtf(ss), 1e-12f);
    qv.x *= inv; qv.y *= inv;
    ((__half2*)(Qh + (size_t)r * D_ + h * HD_))[lane] = __floats2half2_rn(qv.x, qv.y);

    float d = qv.x * gv.x + qv.y * gv.y;
#pragma unroll
    for (int o = 16; o > 0; o >>= 1) d += __shfl_xor_sync(0xffffffffu, d, o);
    if (lane == 0) {
        int b = r / T_, t = r % T_;
        gate[((size_t)b * H_ + h) * T_ + t] = d;
    }
}

// ---------------- fused attention, fp16 mma ----------------
// 64 q-rows/block, 8 warps (2m x 4n), warp S-tile 32x16, k16 mma steps.
// Qs/Ks/Ss [64][72] halves row-major; Vs [s][d] row-major, B-frag via ldsm.trans.
#define AT_S     72
#define AT_TILE  (64 * AT_S)
#define SMEM_ATT (6 * AT_TILE * 2 + (64 + 128) * 4)

__global__ __launch_bounds__(256, 2) void attention_h(const __half* __restrict__ Qh,
                                                      const __half* __restrict__ Kh,
                                                      const __half* __restrict__ Vh,
                                                      const float* __restrict__ GQ,
                                                      const float* __restrict__ GK,
                                                      __half* __restrict__ O) {
    extern __shared__ __half hsm[];
    __half* Qs  = hsm;                      // [64][72]
    __half* Ks0 = Qs  + AT_TILE;            // [2][64][72]
    __half* Vs0 = Ks0 + 2 * AT_TILE;        // [2][64][72]
    __half* Ss  = Vs0 + 2 * AT_TILE;        // [64][72]
    float*  gqs = (float*)(Ss + AT_TILE);   // [64]
    float*  gks = gqs + 64;                 // [2][64]

    int t0  = blockIdx.x * 64;
    int h   = blockIdx.y;
    int b   = blockIdx.z;
    int tid = threadIdx.x;
    int lane = tid & 31, wid = tid >> 5;
    int wm = wid & 1, wn = wid >> 1;
    int l15 = lane & 15, lh8 = (lane >> 4) * 8;

    const size_t base  = (size_t)b * T_ * D_ + h * HD_;
    const size_t gbase = ((size_t)b * H_ + h) * T_;

    // prologue: Q + KV tile 0 via cp.async
#pragma unroll
    for (int j = 0; j < 2; j++) {
        int idx = tid + j * 256;
        int r = idx >> 3, c = (idx & 7) * 8;
        CPA16(&Qs[r * AT_S + c],  Qh + base + (size_t)(t0 + r) * D_ + c);
        CPA16(&Ks0[r * AT_S + c], Kh + base + (size_t)r * D_ + c);
        CPA16(&Vs0[r * AT_S + c], Vh + base + (size_t)r * D_ + c);
    }
    CPC();
    if (tid < 64) {
        gqs[tid] = GQ[gbase + t0 + tid];
        gks[tid] = GK[gbase + tid];
    }

    float acc[2][2][4];
#pragma unroll
    for (int mt = 0; mt < 2; mt++)
#pragma unroll
        for (int nt = 0; nt < 2; nt++)
#pragma unroll
            for (int c = 0; c < 4; c++) acc[mt][nt][c] = 0.f;

    CPW0();
    __syncthreads();

    int buf = 0;
    for (int s0 = 0; s0 < T_; s0 += 64) {
        bool more = (s0 + 64) < T_;
        float gp = 0.f;
        if (more) {
#pragma unroll
            for (int j = 0; j < 2; j++) {
                int idx = tid + j * 256;
                int r = idx >> 3, c = (idx & 7) * 8;
                CPA16(&Ks0[(buf ^ 1) * AT_TILE + r * AT_S + c],
                      Kh + base + (size_t)(s0 + 64 + r) * D_ + c);
                CPA16(&Vs0[(buf ^ 1) * AT_TILE + r * AT_S + c],
                      Vh + base + (size_t)(s0 + 64 + r) * D_ + c);
            }
            CPC();
            if (tid < 64) gp = GK[gbase + s0 + 64 + tid];
        }

        // ---- S = Q @ K^T (k = d, 4 steps of 16) ----
        const __half* Kb = Ks0 + buf * AT_TILE;
        float sacc[2][2][4];
#pragma unroll
        for (int mt = 0; mt < 2; mt++)
#pragma unroll
            for (int nt = 0; nt < 2; nt++)
#pragma unroll
                for (int c = 0; c < 4; c++) sacc[mt][nt][c] = 0.f;

#pragma unroll
        for (int ks = 0; ks < 4; ks++) {
            unsigned af[2][4], bfr[4];
#pragma unroll
            for (int mt = 0; mt < 2; mt++)
                ldsm4(af[mt], Qs + (wm * 32 + mt * 16 + l15) * AT_S + ks * 16 + lh8);
            ldsm4(bfr, Kb + (wn * 16 + l15) * AT_S + ks * 16 + lh8);
#pragma unroll
            for (int mt = 0; mt < 2; mt++) {
                mma16(sacc[mt][0], af[mt], bfr[0], bfr[2]);
                mma16(sacc[mt][1], af[mt], bfr[1], bfr[3]);
            }
        }

        // ---- gate + store S (half) ----
#pragma unroll
        for (int mt = 0; mt < 2; mt++) {
            int qrow = wm * 32 + mt * 16 + (lane >> 2);
            float gq0 = gqs[qrow], gq1 = gqs[qrow + 8];
#pragma unroll
            for (int nt = 0; nt < 2; nt++) {
                int scol = wn * 16 + nt * 8 + 2 * (lane & 3);
                float gk0 = gks[buf * 64 + scol], gk1 = gks[buf * 64 + scol + 1];
                float s0v = 1.f / (1.f + __expf((THRESH - sacc[mt][nt][0]) * SHARP)) * gq0 * gk0;
                float s1v = 1.f / (1.f + __expf((THRESH - sacc[mt][nt][1]) * SHARP)) * gq0 * gk1;
                float s2v = 1.f / (1.f + __expf((THRESH - sacc[mt][nt][2]) * SHARP)) * gq1 * gk0;
                float s3v = 1.f / (1.f + __expf((THRESH - sacc[mt][nt][3]) * SHARP)) * gq1 * gk1;
                *(__half2*)&Ss[qrow * AT_S + scol]       = __floats2half2_rn(s0v, s1v);
                *(__half2*)&Ss[(qrow + 8) * AT_S + scol] = __floats2half2_rn(s2v, s3v);
            }
        }
        __syncthreads();   // Ss visible to all warps
        if (more && tid < 64) gks[(buf ^ 1) * 64 + tid] = gp;

        // ---- C += S @ V (k = s, 4 steps of 16; V via ldsm.trans) ----
        const __half* Vb = Vs0 + buf * AT_TILE;
#pragma unroll
        for (int sq = 0; sq < 4; sq++) {
            unsigned af[2][4], bfr[4];
#pragma unroll
            for (int mt = 0; mt < 2; mt++)
                ldsm4(af[mt], Ss + (wm * 32 + mt * 16 + l15) * AT_S + sq * 16 + lh8);
            ldsm4t(bfr, Vb + (sq * 16 + l15) * AT_S + wn * 16 + lh8);
#pragma unroll
            for (int mt = 0; mt < 2; mt++) {
                mma16(acc[mt][0], af[mt], bfr[0], bfr[1]);
                mma16(acc[mt][1], af[mt], bfr[2], bfr[3]);
            }
        }
        CPW0();
        __syncthreads();   // next K/V arrived; Ss/Vs[buf] consumed
        buf ^= 1;
    }

    // ---- write collapse (half) [b, t, h, d] ----
#pragma unroll
    for (int mt = 0; mt < 2; mt++) {
        int row = wm * 32 + mt * 16 + (lane >> 2);
#pragma unroll
        for (int nt = 0; nt < 2; nt++) {
            int col = wn * 16 + nt * 8 + 2 * (lane & 3);
            *(__half2*)(O + base + (size_t)(t0 + row) * D_ + col) =
                __floats2half2_rn(acc[mt][nt][0], acc[mt][nt][1]);
            *(__half2*)(O + base + (size_t)(t0 + row + 8) * D_ + col) =
                __floats2half2_rn(acc[mt][nt][2], acc[mt][nt][3]);
        }
    }
}

// ---------------- launch ----------------
extern "C" void kernel_launch(void* const* d_in, const int* in_sizes, int n_in,
                              void* d_out, int out_size) {
    const float* x    = (const float*)d_in[0];
    const float* Wq   = (const float*)d_in[1];
    const float* Wk   = (const float*)d_in[2];
    const float* Wv   = (const float*)d_in[3];
    const float* gq   = (const float*)d_in[4];
    const float* gk   = (const float*)d_in[5];
    const float* Wo   = (const float*)d_in[6];
    const float* bo   = (const float*)d_in[7];
    const float* ln_w = (const float*)d_in[8];
    const float* ln_b = (const float*)d_in[9];
    float* out = (float*)d_out;

    __half *xh, *xnh, *vh, *qh, *kh, *collh;
    float *q, *k, *gqb, *gkb;
    cudaGetSymbolAddress((void**)&xh,    g_xh);
    cudaGetSymbolAddress((void**)&xnh,   g_xnh);
    cudaGetSymbolAddress((void**)&vh,    g_vh);
    cudaGetSymbolAddress((void**)&qh,    g_qh);
    cudaGetSymbolAddress((void**)&kh,    g_kh);
    cudaGetSymbolAddress((void**)&collh, g_collh);
    cudaGetSymbolAddress((void**)&q,     g_q);
    cudaGetSymbolAddress((void**)&k,     g_k);
    cudaGetSymbolAddress((void**)&gqb,   g_gq);
    cudaGetSymbolAddress((void**)&gkb,   g_gk);

    cudaFuncSetAttribute(hgemm, cudaFuncAttributeMaxDynamicSharedMemorySize, HG_SMEM);
    cudaFuncSetAttribute(attention_h, cudaFuncAttributeMaxDynamicSharedMemorySize, SMEM_ATT);

    ln_kernel<<<M_, 256>>>(x, ln_w, ln_b, xh, xnh);

    dim3 gGemm(D_ / 128, M_ / 128);
    hgemm<<<gGemm, 256, HG_SMEM>>>(xnh, Wq, nullptr, q, nullptr, M_, D_, D_);
    hgemm<<<gGemm, 256, HG_SMEM>>>(xnh, Wk, nullptr, k, nullptr, M_, D_, D_);
    hgemm<<<gGemm, 256, HG_SMEM>>>(xh,  Wv, nullptr, nullptr, vh, M_, D_, D_);

    int nWarps = M_ * H_;
    norm_gate_kernel<<<(nWarps * 32 + 255) / 256, 256>>>(q, qh, gq, gqb);
    norm_gate_kernel<<<(nWarps * 32 + 255) / 256, 256>>>(k, kh, gk, gkb);

    attention_h<<<dim3(T_ / 64, H_, B_), 256, SMEM_ATT>>>(qh, kh, vh, gqb, gkb, collh);

    hgemm<<<gGemm, 256, HG_SMEM>>>(collh, Wo, bo, out, nullptr, M_, D_, D_);
}